// round 12
// baseline (speedup 1.0000x reference)
#include <cuda_runtime.h>
#include <cuda_fp16.h>

#define N0 20000
#define E0 200000
#define M0 8000
#define E1 80000
#define M1 2000
#define E2 20000
#define M2 500
#define BB 64
#define HH 8
#define EPSV 1e-8f

#define ETOT (E0 + E1 + E2)
#define TP_BLOCKS 1250  /* (20000/32) * (64/32) transpose tiles */
#define EB ((ETOT + 255) / 256)  /* one-edge-per-thread blocks */
#define MAXDEG 96

// ---------------- device scratch (no allocs; zero-init at module load) ----------------
__device__ __half g_xTh[N0 * BB];           // x transposed, fp16: [node][b]
__device__ __half g_dataAh[M0 * BB * HH];   // layer-0 output, fp16
__device__ __half g_dataBh[M1 * BB * HH];   // layer-1 output, fp16
__device__ int g_cnt0[M0], g_cnt1[M1], g_cnt2[M2];  // zero-init; layers re-zero after use
__device__ int g_ell0[M0 * MAXDEG];
__device__ int g_ell1[M1 * MAXDEG];
__device__ int g_ell2[M2 * MAXDEG];

__device__ __forceinline__ void acc8_from_uint4(float* acc, uint4 v) {
    float2 f0 = __half22float2(*(__half2*)&v.x);
    float2 f1 = __half22float2(*(__half2*)&v.y);
    float2 f2 = __half22float2(*(__half2*)&v.z);
    float2 f3 = __half22float2(*(__half2*)&v.w);
    acc[0] += f0.x; acc[1] += f0.y; acc[2] += f1.x; acc[3] += f1.y;
    acc[4] += f2.x; acc[5] += f2.y; acc[6] += f3.x; acc[7] += f3.y;
}

// ---------------- fused: transpose x (fp32->fp16) + one-pass ELL fill ----------------
__global__ void k_prep(const float* __restrict__ x,
                       const int* __restrict__ s0, const int* __restrict__ d0,
                       const int* __restrict__ s1, const int* __restrict__ d1,
                       const int* __restrict__ s2, const int* __restrict__ d2) {
    int b = blockIdx.x;
    int tid = threadIdx.x;
    if (b < TP_BLOCKS) {
        __shared__ float tile[32][33];
        int bx = b % 625, by = b / 625;
        int n0 = bx * 32, b0 = by * 32;
        int tx = tid & 31, ty0 = tid >> 5;
#pragma unroll
        for (int i = 0; i < 32; i += 8) {
            int ty = ty0 + i;
            tile[ty][tx] = x[(size_t)(b0 + ty) * N0 + (n0 + tx)];
        }
        __syncthreads();
#pragma unroll
        for (int i = 0; i < 32; i += 8) {
            int ty = ty0 + i;
            g_xTh[(size_t)(n0 + ty) * BB + (b0 + tx)] =
                __float2half(tile[tx][ty]);
        }
    } else {
        // one edge per thread: load dst, grab slot, scatter src
        int i = (b - TP_BLOCKS) * 256 + tid;
        if (i < E0) {
            int d = d0[i];
            int slot = atomicAdd(&g_cnt0[d], 1);
            g_ell0[d * MAXDEG + slot] = s0[i];
        } else if (i < E0 + E1) {
            int j = i - E0;
            int d = d1[j];
            int slot = atomicAdd(&g_cnt1[d], 1);
            g_ell1[d * MAXDEG + slot] = s1[j];
        } else if (i < ETOT) {
            int j = i - E0 - E1;
            int d = d2[j];
            int slot = atomicAdd(&g_cnt2[d], 1);
            g_ell2[d * MAXDEG + slot] = s2[j];
        }
    }
}

// ---------------- layer 0: warp-per-node, barrier-free; also seeds out[] ----------------
__global__ void k_layer0(const float* __restrict__ W0,
                         const float* __restrict__ bout,
                         float* __restrict__ out) {
    int warp = threadIdx.x >> 5;
    int lane = threadIdx.x & 31;
    int j = blockIdx.x * 8 + warp;
    int sg = lane >> 3, li = lane & 7;  // sg: edge subgroup, li: 16B chunk
    int deg = g_cnt0[j];
    const int* __restrict__ row_ids = g_ell0 + j * MAXDEG;

    // seed out[b] = bout (strictly before layer2's atomics, kernel ordering)
    if (blockIdx.x == 0 && threadIdx.x < BB) out[threadIdx.x] = bout[0];

    // reset cnt for next call (all lanes of this warp have read deg)
    __syncwarp();
    if (lane == 0) g_cnt0[j] = 0;

    float acc[8];
#pragma unroll
    for (int i = 0; i < 8; i++) acc[i] = 0.f;
    for (int k = sg; k < deg; k += 4) {
        const uint4* row = (const uint4*)(g_xTh + ((size_t)row_ids[k] << 6));
        acc8_from_uint4(acc, row[li]);
    }
#pragma unroll
    for (int i = 0; i < 8; i++) {
        acc[i] += __shfl_xor_sync(0xffffffffu, acc[i], 8);
        acc[i] += __shfl_xor_sync(0xffffffffu, acc[i], 16);
    }
    float inv = 1.f / (float)(deg > 0 ? deg : 1);
    float amn = acc[0] * inv, amx = amn;
#pragma unroll
    for (int i = 0; i < 8; i++) {
        float a = acc[i] * inv;
        amn = fminf(amn, a);
        amx = fmaxf(amx, a);
    }
#pragma unroll
    for (int o = 16; o; o >>= 1) {
        amn = fminf(amn, __shfl_xor_sync(0xffffffffu, amn, o));
        amx = fmaxf(amx, __shfl_xor_sync(0xffffffffu, amx, o));
    }

    __shared__ float sAgg[8][64];
    if (sg == 0) {
#pragma unroll
        for (int i = 0; i < 8; i++) sAgg[warp][li * 8 + i] = acc[i] * inv;
    }
    __syncwarp();
    float a0 = sAgg[warp][lane * 2];
    float a1 = sAgg[warp][lane * 2 + 1];

    uint4 st0, st1;
    unsigned* p0 = (unsigned*)&st0;
    unsigned* p1 = (unsigned*)&st1;
#pragma unroll
    for (int hp = 0; hp < 4; hp++) {
        float w0 = W0[hp * 2], w1 = W0[hp * 2 + 1];
        float mn0 = w0 >= 0.f ? w0 * amn : w0 * amx;
        float mx0 = w0 >= 0.f ? w0 * amx : w0 * amn;
        float mn1 = w1 >= 0.f ? w1 * amn : w1 * amx;
        float mx1 = w1 >= 0.f ? w1 * amx : w1 * amn;
        float id0 = 1.f / (mx0 - mn0 + EPSV);
        float id1 = 1.f / (mx1 - mn1 + EPSV);
        float v0a = fmaxf((a0 * w0 - mn0) * id0, 0.f);
        float v1a = fmaxf((a0 * w1 - mn1) * id1, 0.f);
        float v0b = fmaxf((a1 * w0 - mn0) * id0, 0.f);
        float v1b = fmaxf((a1 * w1 - mn1) * id1, 0.f);
        __half2 ha = __floats2half2_rn(v0a, v1a);
        __half2 hb = __floats2half2_rn(v0b, v1b);
        p0[hp] = *(unsigned*)&ha;
        p1[hp] = *(unsigned*)&hb;
    }
    uint4* dst = (uint4*)(g_dataAh + ((size_t)j << 9));
    dst[lane * 2] = st0;
    dst[lane * 2 + 1] = st1;
}

// ---------------- layer 1: 256 thr; 64 lanes(uint4) x 4 groups -> fp16 dataB ----------------
__global__ void k_layer1(const float* __restrict__ W) {
    int j = blockIdx.x, tid = threadIdx.x;
    int lane = tid & 63, grp = tid >> 6;  // 4 groups
    int deg = g_cnt1[j];
    const int* __restrict__ row_ids = g_ell1 + j * MAXDEG;

    float acc[8];
#pragma unroll
    for (int i = 0; i < 8; i++) acc[i] = 0.f;
    int k = grp;
    for (; k + 12 < deg; k += 16) {
        uint4 v0 = ((const uint4*)(g_dataAh + ((size_t)row_ids[k] << 9)))[lane];
        uint4 v1 = ((const uint4*)(g_dataAh + ((size_t)row_ids[k + 4] << 9)))[lane];
        uint4 v2 = ((const uint4*)(g_dataAh + ((size_t)row_ids[k + 8] << 9)))[lane];
        uint4 v3 = ((const uint4*)(g_dataAh + ((size_t)row_ids[k + 12] << 9)))[lane];
        acc8_from_uint4(acc, v0);
        acc8_from_uint4(acc, v1);
        acc8_from_uint4(acc, v2);
        acc8_from_uint4(acc, v3);
    }
    for (; k < deg; k += 4) {
        uint4 v = ((const uint4*)(g_dataAh + ((size_t)row_ids[k] << 9)))[lane];
        acc8_from_uint4(acc, v);
    }

    __shared__ float sP[4][64][8];  // [group][b][h]
    __shared__ float sW[64];
    __shared__ float sMn[2][8], sMx[2][8];
#pragma unroll
    for (int i = 0; i < 8; i++) sP[grp][lane][i] = acc[i];
    if (tid < 64) sW[tid] = W[tid];
    __syncthreads();
    if (tid == 0) g_cnt1[j] = 0;  // reset for next call (deg reads all done)

    float t[8];
    if (tid < 64) {
        float inv = 1.f / (float)(deg > 0 ? deg : 1);
        float a[8];
#pragma unroll
        for (int d = 0; d < 8; d++)
            a[d] = (sP[0][tid][d] + sP[1][tid][d] + sP[2][tid][d] +
                    sP[3][tid][d]) * inv;
        float mn[8], mx[8];
#pragma unroll
        for (int h = 0; h < 8; h++) {
            float s = 0.f;
#pragma unroll
            for (int d = 0; d < 8; d++) s += a[d] * sW[h * 8 + d];
            t[h] = s;
            mn[h] = s;
            mx[h] = s;
        }
#pragma unroll
        for (int o = 16; o; o >>= 1) {
#pragma unroll
            for (int h = 0; h < 8; h++) {
                mn[h] = fminf(mn[h], __shfl_xor_sync(0xffffffffu, mn[h], o));
                mx[h] = fmaxf(mx[h], __shfl_xor_sync(0xffffffffu, mx[h], o));
            }
        }
        if ((tid & 31) == 0) {
            int w = tid >> 5;
#pragma unroll
            for (int h = 0; h < 8; h++) {
                sMn[w][h] = mn[h];
                sMx[w][h] = mx[h];
            }
        }
    }
    __syncthreads();
    float* sOut = &sP[0][0][0];
    if (tid < 64) {
#pragma unroll
        for (int h = 0; h < 8; h++) {
            float mnF = fminf(sMn[0][h], sMn[1][h]);
            float mxF = fmaxf(sMx[0][h], sMx[1][h]);
            float v = (t[h] - mnF) / (mxF - mnF + EPSV);
            sOut[tid * 8 + h] = fmaxf(v, 0.f);
        }
    }
    __syncthreads();
    if (tid < 128) {
        float4 o = ((const float4*)sOut)[tid];
        __half2 h0 = __floats2half2_rn(o.x, o.y);
        __half2 h1 = __floats2half2_rn(o.z, o.w);
        uint2 st;
        st.x = *(unsigned*)&h0;
        st.y = *(unsigned*)&h1;
        ((uint2*)(g_dataBh + ((size_t)j << 9)))[tid] = st;
    }
}

// ---------------- layer 2: 256 thr; fused final dot -> atomicAdd out ----------------
__global__ void k_layer2(const float* __restrict__ W,
                         const float* __restrict__ Wout,
                         float* __restrict__ out) {
    int j = blockIdx.x, tid = threadIdx.x;
    int lane = tid & 63, grp = tid >> 6;  // 4 groups
    int deg = g_cnt2[j];
    const int* __restrict__ row_ids = g_ell2 + j * MAXDEG;

    float acc[8];
#pragma unroll
    for (int i = 0; i < 8; i++) acc[i] = 0.f;
    int k = grp;
    for (; k + 12 < deg; k += 16) {
        uint4 v0 = ((const uint4*)(g_dataBh + ((size_t)row_ids[k] << 9)))[lane];
        uint4 v1 = ((const uint4*)(g_dataBh + ((size_t)row_ids[k + 4] << 9)))[lane];
        uint4 v2 = ((const uint4*)(g_dataBh + ((size_t)row_ids[k + 8] << 9)))[lane];
        uint4 v3 = ((const uint4*)(g_dataBh + ((size_t)row_ids[k + 12] << 9)))[lane];
        acc8_from_uint4(acc, v0);
        acc8_from_uint4(acc, v1);
        acc8_from_uint4(acc, v2);
        acc8_from_uint4(acc, v3);
    }
    for (; k < deg; k += 4) {
        uint4 v = ((const uint4*)(g_dataBh + ((size_t)row_ids[k] << 9)))[lane];
        acc8_from_uint4(acc, v);
    }

    __shared__ float sP[4][64][8];  // [group][b][h]
    __shared__ float sW[64];
    __shared__ float sMn[2][8], sMx[2][8];
#pragma unroll
    for (int i = 0; i < 8; i++) sP[grp][lane][i] = acc[i];
    if (tid < 64) sW[tid] = W[tid];
    __syncthreads();
    if (tid == 0) g_cnt2[j] = 0;  // reset for next call

    float t[8];
    if (tid < 64) {
        float inv = 1.f / (float)(deg > 0 ? deg : 1);
        float a[8];
#pragma unroll
        for (int d = 0; d < 8; d++)
            a[d] = (sP[0][tid][d] + sP[1][tid][d] + sP[2][tid][d] +
                    sP[3][tid][d]) * inv;
        float mn[8], mx[8];
#pragma unroll
        for (int h = 0; h < 8; h++) {
            float s = 0.f;
#pragma unroll
            for (int d = 0; d < 8; d++) s += a[d] * sW[h * 8 + d];
            t[h] = s;
            mn[h] = s;
            mx[h] = s;
        }
#pragma unroll
        for (int o = 16; o; o >>= 1) {
#pragma unroll
            for (int h = 0; h < 8; h++) {
                mn[h] = fminf(mn[h], __shfl_xor_sync(0xffffffffu, mn[h], o));
                mx[h] = fmaxf(mx[h], __shfl_xor_sync(0xffffffffu, mx[h], o));
            }
        }
        if ((tid & 31) == 0) {
            int w = tid >> 5;
#pragma unroll
            for (int h = 0; h < 8; h++) {
                sMn[w][h] = mn[h];
                sMx[w][h] = mx[h];
            }
        }
    }
    __syncthreads();  // cross-warp visibility of sMn/sMx (warps 0 and 1)
    if (tid < 64) {
        float p = 0.f;
#pragma unroll
        for (int h = 0; h < 8; h++) {
            float mnF = fminf(sMn[0][h], sMn[1][h]);
            float mxF = fmaxf(sMx[0][h], sMx[1][h]);
            float v = (t[h] - mnF) / (mxF - mnF + EPSV);
            p += fmaxf(v, 0.f) * Wout[j * 8 + h];
        }
        atomicAdd(&out[tid], p);
    }
}

// ---------------- host ----------------
extern "C" void kernel_launch(void* const* d_in, const int* in_sizes, int n_in,
                              void* d_out, int out_size) {
    const float *x = 0, *W0 = 0, *W1 = 0, *W2 = 0, *Wout = 0, *bout = 0;
    const int *s0 = 0, *d0 = 0, *s1 = 0, *d1 = 0, *s2 = 0, *d2 = 0;
    for (int i = 0; i < n_in; i++) {
        int sz = in_sizes[i];
        const void* p = d_in[i];
        if (sz == BB * N0) x = (const float*)p;
        else if (sz == E0) { if (!s0) s0 = (const int*)p; else d0 = (const int*)p; }
        else if (sz == E1) { if (!s1) s1 = (const int*)p; else d1 = (const int*)p; }
        else if (sz == E2) { if (!s2) s2 = (const int*)p; else d2 = (const int*)p; }
        else if (sz == HH) W0 = (const float*)p;
        else if (sz == HH * HH) { if (!W1) W1 = (const float*)p; else W2 = (const float*)p; }
        else if (sz == M2 * HH) Wout = (const float*)p;
        else if (sz == 1) bout = (const float*)p;
    }
    float* out = (float*)d_out;

    k_prep<<<TP_BLOCKS + EB + 1, 256>>>(x, s0, d0, s1, d1, s2, d2);
    k_layer0<<<M0 / 8, 256>>>(W0, bout, out);
    k_layer1<<<M1, 256>>>(W1);
    k_layer2<<<M2, 256>>>(W2, Wout, out);
}